// round 12
// baseline (speedup 1.0000x reference)
#include <cuda_runtime.h>
#include <cstdint>

#define Tn 4000
#define Bn 16
#define Cn 256
#define G4 1024        // 4*C
#define Mn (Tn*Bn)     // 64000
#define NLAYER 12
#define NBPC 2         // batches per cluster
#define NCLUSTER (Bn / NBPC)   // 8 clusters of 8 CTAs = 64 CTAs (single wave)

// ---------------- scratch (device globals: allocation-free) ----------------
__device__ float g_Xa[(size_t)Mn * Cn];
__device__ float g_Xb[(size_t)Mn * Cn];
__device__ float g_GX[(size_t)Mn * G4];
__device__ float g_bias[NLAYER * G4];

// ---------------- packed f32x2 helpers ----------------
__device__ __forceinline__ void ffma2(unsigned long long& d, unsigned long long a, unsigned long long b) {
    asm("fma.rn.f32x2 %0, %1, %2, %0;" : "+l"(d) : "l"(a), "l"(b));
}
__device__ __forceinline__ unsigned long long pk(float a, float b) {
    unsigned long long r; asm("mov.b64 %0, {%1,%2};" : "=l"(r) : "f"(a), "f"(b)); return r;
}
__device__ __forceinline__ float2 unpk(unsigned long long v) {
    float2 r; asm("mov.b64 {%0,%1}, %2;" : "=f"(r.x), "=f"(r.y) : "l"(v)); return r;
}

// MUFU.TANH — single HW op (~1e-5 err); R10 confirmed rel_err 2.7e-6 overall
__device__ __forceinline__ float tanh_mufu(float x) {
    float r; asm("tanh.approx.f32 %0, %1;" : "=f"(r) : "f"(x)); return r;
}
__device__ __forceinline__ float sig_mufu(float x) {
    return fmaf(0.5f, tanh_mufu(0.5f * x), 0.5f);
}

// ---------------- cluster primitives ----------------
__device__ __forceinline__ void st_peer(unsigned laddr, unsigned peer, float v) {
    asm volatile(
        "{\n\t.reg .u32 ra;\n\t"
        "mapa.shared::cluster.u32 ra, %0, %1;\n\t"
        "st.shared::cluster.f32 [ra], %2;\n\t}"
        :: "r"(laddr), "r"(peer), "f"(v) : "memory");
}
#define CLUSTER_SYNC() do { \
    asm volatile("barrier.cluster.arrive.aligned;" ::: "memory"); \
    asm volatile("barrier.cluster.wait.aligned;" ::: "memory"); } while (0)

// ---------------- tiny bias precompute ----------------
__global__ void bias_kernel(const float* __restrict__ bih, const float* __restrict__ bhh,
                            float* __restrict__ out) {
    int i = blockIdx.x * 256 + threadIdx.x;
    out[i] = bih[i] + bhh[i];
}

// ---------------- transpose in: x(B,C,L) -> X[t][b][c] ----------------
__global__ void tin_kernel(const float* __restrict__ x, float* __restrict__ X) {
    __shared__ float tile[32][33];
    int t0 = blockIdx.x * 32, c0 = blockIdx.y * 32, b = blockIdx.z;
    int tx = threadIdx.x, ty = threadIdx.y;
    #pragma unroll
    for (int i = 0; i < 32; i += 8)
        tile[ty + i][tx] = x[(size_t)b * Cn * Tn + (size_t)(c0 + ty + i) * Tn + t0 + tx];
    __syncthreads();
    #pragma unroll
    for (int i = 0; i < 32; i += 8)
        X[(size_t)(t0 + ty + i) * Bn * Cn + b * Cn + c0 + tx] = tile[tx][ty + i];
}

// ---------------- transpose out: X[t][b][c] -> out(B,C,L) ----------------
__global__ void tout_kernel(const float* __restrict__ X, float* __restrict__ out) {
    __shared__ float tile[32][33];
    int t0 = blockIdx.x * 32, c0 = blockIdx.y * 32, b = blockIdx.z;
    int tx = threadIdx.x, ty = threadIdx.y;
    #pragma unroll
    for (int i = 0; i < 32; i += 8)
        tile[ty + i][tx] = X[(size_t)(t0 + ty + i) * Bn * Cn + b * Cn + c0 + tx];
    __syncthreads();
    #pragma unroll
    for (int i = 0; i < 32; i += 8)
        out[(size_t)b * Cn * Tn + (size_t)(c0 + ty + i) * Tn + t0 + tx] = tile[tx][ty + i];
}

// ---------------- gx GEMM: GX[m][n] = X[m][k]*W[n][k] + bias[n] ----------------
__global__ __launch_bounds__(256, 2) void gemm_gx(
    const float* __restrict__ X, const float* __restrict__ W,
    const float* __restrict__ bsum, float* __restrict__ GXo)
{
    __shared__ __align__(16) float As[2][8][128];
    __shared__ __align__(16) float Bs[2][8][128];
    const int m0 = blockIdx.y * 128;
    const int n0 = blockIdx.x * 128;
    const int tid = threadIdx.x;
    const int tx = tid & 15, ty = tid >> 4;
    const int lr = tid >> 1;           // 0..127
    const int lk = (tid & 1) * 4;      // 0 or 4

    const float* Ag = X + (size_t)(m0 + lr) * 256 + lk;
    const float* Bg = W + (size_t)(n0 + lr) * 256 + lk;

    auto load_stage = [&](int s, int kc) {
        float4 av = *reinterpret_cast<const float4*>(Ag + kc * 8);
        float4 bv = *reinterpret_cast<const float4*>(Bg + kc * 8);
        As[s][lk + 0][lr] = av.x; As[s][lk + 1][lr] = av.y;
        As[s][lk + 2][lr] = av.z; As[s][lk + 3][lr] = av.w;
        Bs[s][lk + 0][lr] = bv.x; Bs[s][lk + 1][lr] = bv.y;
        Bs[s][lk + 2][lr] = bv.z; Bs[s][lk + 3][lr] = bv.w;
    };

    unsigned long long acc[8][4];
    #pragma unroll
    for (int i = 0; i < 8; i++)
        #pragma unroll
        for (int j = 0; j < 4; j++) acc[i][j] = 0ull;

    load_stage(0, 0);
    __syncthreads();

    for (int kc = 0; kc < 32; ++kc) {
        int s = kc & 1;
        if (kc < 31) load_stage(s ^ 1, kc + 1);
        #pragma unroll
        for (int k = 0; k < 8; k++) {
            float4 a0 = *reinterpret_cast<const float4*>(&As[s][k][ty * 8]);
            float4 a1 = *reinterpret_cast<const float4*>(&As[s][k][ty * 8 + 4]);
            float4 b0 = *reinterpret_cast<const float4*>(&Bs[s][k][tx * 8]);
            float4 b1 = *reinterpret_cast<const float4*>(&Bs[s][k][tx * 8 + 4]);
            unsigned long long bb0 = pk(b0.x, b0.y), bb1 = pk(b0.z, b0.w);
            unsigned long long bb2 = pk(b1.x, b1.y), bb3 = pk(b1.z, b1.w);
            float av[8] = {a0.x, a0.y, a0.z, a0.w, a1.x, a1.y, a1.z, a1.w};
            #pragma unroll
            for (int i = 0; i < 8; i++) {
                unsigned long long aa = pk(av[i], av[i]);
                ffma2(acc[i][0], aa, bb0);
                ffma2(acc[i][1], aa, bb1);
                ffma2(acc[i][2], aa, bb2);
                ffma2(acc[i][3], aa, bb3);
            }
        }
        __syncthreads();
    }

    float bias[8];
    #pragma unroll
    for (int j = 0; j < 8; j++) bias[j] = __ldg(&bsum[n0 + tx * 8 + j]);
    #pragma unroll
    for (int i = 0; i < 8; i++) {
        size_t m = (size_t)(m0 + ty * 8 + i);
        float o[8];
        #pragma unroll
        for (int jp = 0; jp < 4; jp++) {
            float2 v = unpk(acc[i][jp]);
            o[2 * jp] = v.x + bias[2 * jp];
            o[2 * jp + 1] = v.y + bias[2 * jp + 1];
        }
        float4* dst = reinterpret_cast<float4*>(&GXo[m * 1024 + n0 + tx * 8]);
        dst[0] = make_float4(o[0], o[1], o[2], o[3]);
        dst[1] = make_float4(o[4], o[5], o[6], o[7]);
    }
}

// ---------------- persistent LSTM scan: 512 threads, K-quarter lanes --------
// 8 clusters of 8 CTAs (64 CTAs, single wave); cluster cl = batches {2cl,2cl+1}.
// CTA rank owns units [rank*32, rank*32+32). 512 threads / 16 warps.
// Lane bits: [4]=u_local, [3:2]=s (gate), [1:0]=kq (K-quarter).
//   unit = warp*2 + u_local, col = rank*32+unit, grow = s*256+col.
// Per step (R7 skeleton): prefetch -> K-quarter dot for BOTH batches
// (64 FFMA2 + 32 LDS.128, rotation-swizzled -> conflict-free) ->
// shfl.xor(1)+(2) folds (all 4 kq lanes get both full dots) -> lane's batch
// = kq&1 -> MUFU activation -> 4-shfl gate gather -> (c,h) update replicated
// across the (unit,batch)'s 8 lanes -> each pushes hv to one cluster CTA
// (pidx = 2s+(kq>>1)) -> fused barrier.cluster.
__global__ void __cluster_dims__(8, 1, 1) __launch_bounds__(512, 1)
scan_kernel(const float* __restrict__ Xin, const float* __restrict__ GX,
            const float* __restrict__ Whh, float* __restrict__ Xout, int is_even)
{
    unsigned rank;
    asm("mov.u32 %0, %%cluster_ctarank;" : "=r"(rank));
    const int cl = blockIdx.x >> 3;
    const int b0 = cl * NBPC;
    const int tid = threadIdx.x;
    const int warp = tid >> 5, lane = tid & 31;
    const int u_local = lane >> 4;                 // 0/1
    const int s = (lane >> 2) & 3;                 // gate (i,f,g,o)
    const int kq = lane & 3;                       // K-quarter
    const int unit = warp * 2 + u_local;           // 0..31
    const int col = (int)rank * 32 + unit;         // hidden index 0..255
    const int grow = s * 256 + col;                // W_hh row
    const int bl = kq & 1;                         // lane's batch (local)
    const int bsel = b0 + bl;

    __shared__ __align__(16) float h_s[2][NBPC][256];

    // K-quarter weights, loaded in the SAME rotated order as the h reads
    // (rotation (j+2*kq)&15 spreads the 4 kq address groups across banks)
    ulonglong2 w[16];
    const ulonglong2* wp = reinterpret_cast<const ulonglong2*>(Whh + (size_t)grow * 256 + kq * 64);
    #pragma unroll
    for (int j = 0; j < 16; j++) w[j] = wp[(j + 2 * kq) & 15];

    h_s[0][tid >> 8][tid & 255] = 0.f;
    float c_state = 0.f;
    __syncthreads();
    CLUSTER_SYNC();

    const float* gxp = GX + (size_t)bsel * G4 + grow;
    float gxv = __ldg(gxp);
    auto src_of = [&](int t) { return is_even ? (t % 400) * 10 + (t / 400) : t; };
    const bool writer = (s == 3 && (kq >> 1) == 1);   // one lane per (unit,batch)
    float xres = writer ? __ldg(Xin + ((size_t)src_of(0) * Bn + bsel) * Cn + col) : 0.f;

    const unsigned pidx = (unsigned)(s * 2 + (kq >> 1));   // 0..7 within group
    const unsigned dr = (rank + pidx) & 7u;                 // push target (incl self)

    for (int t = 0; t < Tn; ++t) {
        const int par = t & 1;

        // prefetch next step's gx/xres (flight overlaps dot + barrier)
        float gxn = 0.f, xresn = 0.f;
        if (t + 1 < Tn) {
            gxn = __ldg(gxp + (size_t)(t + 1) * (Bn * G4));
            if (writer)
                xresn = __ldg(Xin + ((size_t)src_of(t + 1) * Bn + bsel) * Cn + col);
        }

        // both-batch dot over this lane's K-quarter (64 FFMA2, 32 LDS.128)
        const ulonglong2* hA = reinterpret_cast<const ulonglong2*>(&h_s[par][0][kq << 6]);
        const ulonglong2* hB = reinterpret_cast<const ulonglong2*>(&h_s[par][1][kq << 6]);
        unsigned long long a00 = 0, a01 = 0, a10 = 0, a11 = 0;
        #pragma unroll
        for (int j = 0; j < 16; j++) {
            const int i = (j + 2 * kq) & 15;       // rotated: conflict-free LDS
            ulonglong2 xA = hA[i], xB = hB[i];
            ffma2(a00, w[j].x, xA.x); ffma2(a01, w[j].y, xA.y);
            ffma2(a10, w[j].x, xB.x); ffma2(a11, w[j].y, xB.y);
        }
        float2 f0 = unpk(a00), f1 = unpk(a01);
        float p0 = (f0.x + f0.y) + (f1.x + f1.y);
        float2 f2 = unpk(a10), f3 = unpk(a11);
        float p1 = (f2.x + f2.y) + (f3.x + f3.y);
        // fold the 4 K-quarters (lanes base..base+3 all end with full dots)
        p0 += __shfl_xor_sync(0xffffffffu, p0, 1);
        p0 += __shfl_xor_sync(0xffffffffu, p0, 2);
        p1 += __shfl_xor_sync(0xffffffffu, p1, 1);
        p1 += __shfl_xor_sync(0xffffffffu, p1, 2);

        // lane's batch = kq&1; one gate activation per lane (MUFU)
        float tot = (bl ? p1 : p0) + gxv;
        float act = (s == 2) ? tanh_mufu(tot) : sig_mufu(tot);
        gxv = gxn;

        // gather this unit's 4 gates (same u_local, same kq)
        const int base = lane & ~12;
        float iv = __shfl_sync(0xffffffffu, act, base);
        float fv = __shfl_sync(0xffffffffu, act, base | 4);
        float gv = __shfl_sync(0xffffffffu, act, base | 8);
        float ov = __shfl_sync(0xffffffffu, act, base | 12);

        c_state = fv * c_state + iv * gv;          // replicated across 8 lanes
        float hv = ov * tanh_mufu(c_state);

        if (t + 1 < Tn) {
            // the (unit,batch)'s 8 replicated lanes cover all 8 cluster CTAs
            unsigned laddr = (unsigned)__cvta_generic_to_shared(&h_s[par ^ 1][bl][col]);
            st_peer(laddr, dr, hv);
        }
        if (writer) {
            const int dst = is_even ? (t % 400) * 10 + (t / 400) : (Tn - 1 - t);
            Xout[((size_t)dst * Bn + bsel) * Cn + col] = xres + hv;
        }
        xres = xresn;

        CLUSTER_SYNC();   // publishes all DSMEM pushes for step t+1
    }
}

// ---------------- launch ----------------
extern "C" void kernel_launch(void* const* d_in, const int* in_sizes, int n_in,
                              void* d_out, int out_size) {
    const float* x    = (const float*)d_in[0];
    const float* w_ih = (const float*)d_in[1];
    const float* w_hh = (const float*)d_in[2];
    const float* b_ih = (const float*)d_in[3];
    const float* b_hh = (const float*)d_in[4];

    float *Xa, *Xb, *GXp, *Bp;
    cudaGetSymbolAddress((void**)&Xa, g_Xa);
    cudaGetSymbolAddress((void**)&Xb, g_Xb);
    cudaGetSymbolAddress((void**)&GXp, g_GX);
    cudaGetSymbolAddress((void**)&Bp, g_bias);
    float* Xbuf[2] = {Xa, Xb};

    bias_kernel<<<NLAYER * G4 / 256, 256>>>(b_ih, b_hh, Bp);

    dim3 tgrid(Tn / 32, Cn / 32, Bn), tblk(32, 8);
    tin_kernel<<<tgrid, tblk>>>(x, Xbuf[0]);

    int cur = 0;
    for (int l = 0; l < NLAYER; ++l) {
        gemm_gx<<<dim3(G4 / 128, Mn / 128), 256>>>(
            Xbuf[cur], w_ih + (size_t)l * G4 * Cn, Bp + (size_t)l * G4, GXp);
        scan_kernel<<<NCLUSTER * 8, 512>>>(
            Xbuf[cur], GXp, w_hh + (size_t)l * G4 * Cn,
            Xbuf[cur ^ 1], (l & 1) == 0 ? 1 : 0);
        cur ^= 1;
    }

    tout_kernel<<<tgrid, tblk>>>(Xbuf[cur], (float*)d_out);
}

// round 14
// speedup vs baseline: 1.8316x; 1.8316x over previous
#include <cuda_runtime.h>
#include <cstdint>

#define Tn 4000
#define Bn 16
#define Cn 256
#define G4 1024        // 4*C
#define Mn (Tn*Bn)     // 64000
#define NLAYER 12
#define NBPC 2         // batches per cluster
#define NCLUSTER (Bn / NBPC)   // 8 clusters of 8 CTAs = 64 CTAs (single wave)

// ---------------- scratch (device globals: allocation-free) ----------------
__device__ float g_Xa[(size_t)Mn * Cn];
__device__ float g_Xb[(size_t)Mn * Cn];
__device__ float g_GX[(size_t)Mn * G4];
__device__ float g_bias[NLAYER * G4];

// ---------------- packed f32x2 helpers ----------------
__device__ __forceinline__ void ffma2(unsigned long long& d, unsigned long long a, unsigned long long b) {
    asm("fma.rn.f32x2 %0, %1, %2, %0;" : "+l"(d) : "l"(a), "l"(b));
}
__device__ __forceinline__ unsigned long long pk(float a, float b) {
    unsigned long long r; asm("mov.b64 %0, {%1,%2};" : "=l"(r) : "f"(a), "f"(b)); return r;
}
__device__ __forceinline__ float2 unpk(unsigned long long v) {
    float2 r; asm("mov.b64 {%0,%1}, %2;" : "=f"(r.x), "=f"(r.y) : "l"(v)); return r;
}

// MUFU.TANH activations — single 16-cyc HW op; rel_err ~2.7e-6 end-to-end
// (validated R10/R11/R12), far inside the 1e-3 budget.
__device__ __forceinline__ float tanh_mufu(float x) {
    float r; asm("tanh.approx.f32 %0, %1;" : "=f"(r) : "f"(x)); return r;
}
__device__ __forceinline__ float sig_mufu(float x) {
    return fmaf(0.5f, tanh_mufu(0.5f * x), 0.5f);
}

// ---------------- cluster primitives ----------------
__device__ __forceinline__ void st_peer(unsigned laddr, unsigned peer, float v) {
    asm volatile(
        "{\n\t.reg .u32 ra;\n\t"
        "mapa.shared::cluster.u32 ra, %0, %1;\n\t"
        "st.shared::cluster.f32 [ra], %2;\n\t}"
        :: "r"(laddr), "r"(peer), "f"(v) : "memory");
}
#define CLUSTER_SYNC() do { \
    asm volatile("barrier.cluster.arrive.aligned;" ::: "memory"); \
    asm volatile("barrier.cluster.wait.aligned;" ::: "memory"); } while (0)

// ---------------- tiny bias precompute ----------------
__global__ void bias_kernel(const float* __restrict__ bih, const float* __restrict__ bhh,
                            float* __restrict__ out) {
    int i = blockIdx.x * 256 + threadIdx.x;
    out[i] = bih[i] + bhh[i];
}

// ---------------- transpose in: x(B,C,L) -> X[t][b][c] ----------------
__global__ void tin_kernel(const float* __restrict__ x, float* __restrict__ X) {
    __shared__ float tile[32][33];
    int t0 = blockIdx.x * 32, c0 = blockIdx.y * 32, b = blockIdx.z;
    int tx = threadIdx.x, ty = threadIdx.y;
    #pragma unroll
    for (int i = 0; i < 32; i += 8)
        tile[ty + i][tx] = x[(size_t)b * Cn * Tn + (size_t)(c0 + ty + i) * Tn + t0 + tx];
    __syncthreads();
    #pragma unroll
    for (int i = 0; i < 32; i += 8)
        X[(size_t)(t0 + ty + i) * Bn * Cn + b * Cn + c0 + tx] = tile[tx][ty + i];
}

// ---------------- transpose out: X[t][b][c] -> out(B,C,L) ----------------
__global__ void tout_kernel(const float* __restrict__ X, float* __restrict__ out) {
    __shared__ float tile[32][33];
    int t0 = blockIdx.x * 32, c0 = blockIdx.y * 32, b = blockIdx.z;
    int tx = threadIdx.x, ty = threadIdx.y;
    #pragma unroll
    for (int i = 0; i < 32; i += 8)
        tile[ty + i][tx] = X[(size_t)(t0 + ty + i) * Bn * Cn + b * Cn + c0 + tx];
    __syncthreads();
    #pragma unroll
    for (int i = 0; i < 32; i += 8)
        out[(size_t)b * Cn * Tn + (size_t)(c0 + ty + i) * Tn + t0 + tx] = tile[tx][ty + i];
}

// ---------------- gx GEMM: GX[m][n] = X[m][k]*W[n][k] + bias[n] ----------------
__global__ __launch_bounds__(256, 2) void gemm_gx(
    const float* __restrict__ X, const float* __restrict__ W,
    const float* __restrict__ bsum, float* __restrict__ GXo)
{
    __shared__ __align__(16) float As[2][8][128];
    __shared__ __align__(16) float Bs[2][8][128];
    const int m0 = blockIdx.y * 128;
    const int n0 = blockIdx.x * 128;
    const int tid = threadIdx.x;
    const int tx = tid & 15, ty = tid >> 4;
    const int lr = tid >> 1;           // 0..127
    const int lk = (tid & 1) * 4;      // 0 or 4

    const float* Ag = X + (size_t)(m0 + lr) * 256 + lk;
    const float* Bg = W + (size_t)(n0 + lr) * 256 + lk;

    auto load_stage = [&](int s, int kc) {
        float4 av = *reinterpret_cast<const float4*>(Ag + kc * 8);
        float4 bv = *reinterpret_cast<const float4*>(Bg + kc * 8);
        As[s][lk + 0][lr] = av.x; As[s][lk + 1][lr] = av.y;
        As[s][lk + 2][lr] = av.z; As[s][lk + 3][lr] = av.w;
        Bs[s][lk + 0][lr] = bv.x; Bs[s][lk + 1][lr] = bv.y;
        Bs[s][lk + 2][lr] = bv.z; Bs[s][lk + 3][lr] = bv.w;
    };

    unsigned long long acc[8][4];
    #pragma unroll
    for (int i = 0; i < 8; i++)
        #pragma unroll
        for (int j = 0; j < 4; j++) acc[i][j] = 0ull;

    load_stage(0, 0);
    __syncthreads();

    for (int kc = 0; kc < 32; ++kc) {
        int s = kc & 1;
        if (kc < 31) load_stage(s ^ 1, kc + 1);
        #pragma unroll
        for (int k = 0; k < 8; k++) {
            float4 a0 = *reinterpret_cast<const float4*>(&As[s][k][ty * 8]);
            float4 a1 = *reinterpret_cast<const float4*>(&As[s][k][ty * 8 + 4]);
            float4 b0 = *reinterpret_cast<const float4*>(&Bs[s][k][tx * 8]);
            float4 b1 = *reinterpret_cast<const float4*>(&Bs[s][k][tx * 8 + 4]);
            unsigned long long bb0 = pk(b0.x, b0.y), bb1 = pk(b0.z, b0.w);
            unsigned long long bb2 = pk(b1.x, b1.y), bb3 = pk(b1.z, b1.w);
            float av[8] = {a0.x, a0.y, a0.z, a0.w, a1.x, a1.y, a1.z, a1.w};
            #pragma unroll
            for (int i = 0; i < 8; i++) {
                unsigned long long aa = pk(av[i], av[i]);
                ffma2(acc[i][0], aa, bb0);
                ffma2(acc[i][1], aa, bb1);
                ffma2(acc[i][2], aa, bb2);
                ffma2(acc[i][3], aa, bb3);
            }
        }
        __syncthreads();
    }

    float bias[8];
    #pragma unroll
    for (int j = 0; j < 8; j++) bias[j] = __ldg(&bsum[n0 + tx * 8 + j]);
    #pragma unroll
    for (int i = 0; i < 8; i++) {
        size_t m = (size_t)(m0 + ty * 8 + i);
        float o[8];
        #pragma unroll
        for (int jp = 0; jp < 4; jp++) {
            float2 v = unpk(acc[i][jp]);
            o[2 * jp] = v.x + bias[2 * jp];
            o[2 * jp + 1] = v.y + bias[2 * jp + 1];
        }
        float4* dst = reinterpret_cast<float4*>(&GXo[m * 1024 + n0 + tx * 8]);
        dst[0] = make_float4(o[0], o[1], o[2], o[3]);
        dst[1] = make_float4(o[4], o[5], o[6], o[7]);
    }
}

// ---------------- persistent LSTM scan (R7 skeleton, MUFU activations) ------
// 8 clusters of 8 CTAs (64 CTAs, single wave); cluster cl advances batches
// {2cl, 2cl+1}. Lane layout: s = lane&3 (gate), kh = lane>>4 (K-half = batch),
// unit = warp*4 + ((lane>>2)&3), col = rank*32+unit. Per step:
//   prefetch gx/xres -> both-batch dot over K-half (128 FFMA2 + 64 LDS.128)
//   -> shfl.xor(16) fold -> MUFU gate activation -> 4-shfl gate gather ->
//   (c,h) update replicated across the unit's 8 lanes -> peer pushes
//   (s -> {s+1, s+5}) -> fused barrier.cluster at loop bottom.
__global__ void __cluster_dims__(8, 1, 1) __launch_bounds__(256, 1)
scan_kernel(const float* __restrict__ Xin, const float* __restrict__ GX,
            const float* __restrict__ Whh, float* __restrict__ Xout, int is_even)
{
    unsigned rank;
    asm("mov.u32 %0, %%cluster_ctarank;" : "=r"(rank));
    const int cl = blockIdx.x >> 3;
    const int b0 = cl * NBPC;
    const int tid = threadIdx.x;
    const int warp = tid >> 5, lane = tid & 31;
    const int s = lane & 3;                        // gate (i,f,g,o)
    const int kh = lane >> 4;                      // K-half = batch index
    const int unit = warp * 4 + ((lane >> 2) & 3); // 0..31
    const int col = (int)rank * 32 + unit;         // hidden index 0..255
    const int grow = s * 256 + col;                // W_hh row
    const int bsel = b0 + kh;

    __shared__ __align__(16) float h_s[2][NBPC][256];

    // K-half weights for this lane's gate row: 128 fp32 register-resident
    ulonglong2 w[32];
    const ulonglong2* wp = reinterpret_cast<const ulonglong2*>(Whh + (size_t)grow * 256 + kh * 128);
    #pragma unroll
    for (int i = 0; i < 32; i++) w[i] = wp[i];

    h_s[0][0][tid] = 0.f;
    h_s[0][1][tid] = 0.f;
    float c_state = 0.f;
    __syncthreads();
    CLUSTER_SYNC();

    const float* gxp = GX + (size_t)bsel * G4 + grow;
    float gxv = __ldg(gxp);
    auto src_of = [&](int t) { return is_even ? (t % 400) * 10 + (t / 400) : t; };
    const bool writer = (s == 1);   // one lane per (unit,batch) writes Xout
    float xres = writer ? __ldg(Xin + ((size_t)src_of(0) * Bn + bsel) * Cn + col) : 0.f;

    for (int t = 0; t < Tn; ++t) {
        const int par = t & 1;

        // prefetch next step's gx/xres (LDG flight overlaps dot + barrier)
        float gxn = 0.f, xresn = 0.f;
        if (t + 1 < Tn) {
            gxn = __ldg(gxp + (size_t)(t + 1) * (Bn * G4));
            if (writer)
                xresn = __ldg(Xin + ((size_t)src_of(t + 1) * Bn + bsel) * Cn + col);
        }

        // both-batch dot over this lane's K-half (128 FFMA2, 64 LDS.128)
        const ulonglong2* hA = reinterpret_cast<const ulonglong2*>(&h_s[par][0][kh << 7]);
        const ulonglong2* hB = reinterpret_cast<const ulonglong2*>(&h_s[par][1][kh << 7]);
        unsigned long long a00 = 0, a01 = 0, a10 = 0, a11 = 0;
        #pragma unroll
        for (int i = 0; i < 32; i++) {
            ulonglong2 xA = hA[i], xB = hB[i];
            ffma2(a00, w[i].x, xA.x); ffma2(a01, w[i].y, xA.y);
            ffma2(a10, w[i].x, xB.x); ffma2(a11, w[i].y, xB.y);
        }
        float2 f0 = unpk(a00), f1 = unpk(a01);
        float p0 = (f0.x + f0.y) + (f1.x + f1.y);
        float2 f2 = unpk(a10), f3 = unpk(a11);
        float p1 = (f2.x + f2.y) + (f3.x + f3.y);
        p0 += __shfl_xor_sync(0xffffffffu, p0, 16);   // fold K-halves
        p1 += __shfl_xor_sync(0xffffffffu, p1, 16);

        // lane's batch = kh; one gate activation per lane (MUFU.TANH)
        float tot = (kh ? p1 : p0) + gxv;
        float act = (s == 2) ? tanh_mufu(tot) : sig_mufu(tot);
        gxv = gxn;

        // gather the 4 gates of this unit (within same kh group)
        const int base = lane & ~3;
        float iv = __shfl_sync(0xffffffffu, act, base);
        float fv = __shfl_sync(0xffffffffu, act, base | 1);
        float gv = __shfl_sync(0xffffffffu, act, base | 2);
        float ov = __shfl_sync(0xffffffffu, act, base | 3);

        c_state = fv * c_state + iv * gv;             // replicated across lanes
        float hv = ov * tanh_mufu(c_state);

        const int nb = par ^ 1;
        if (s == 0) h_s[nb][kh][col] = hv;            // local copy
        if (t + 1 < Tn) {
            // lane's gate slot covers peers {s+1, s+5}: all 7 peers covered
            unsigned laddr = (unsigned)__cvta_generic_to_shared(&h_s[nb][kh][col]);
            st_peer(laddr, (rank + (unsigned)s + 1u) & 7u, hv);
            if (s < 3)
                st_peer(laddr, (rank + (unsigned)s + 5u) & 7u, hv);
        }
        if (writer) {
            const int dst = is_even ? (t % 400) * 10 + (t / 400) : (Tn - 1 - t);
            Xout[((size_t)dst * Bn + bsel) * Cn + col] = xres + hv;
        }
        xres = xresn;

        CLUSTER_SYNC();   // publishes all DSMEM pushes for step t+1
    }
}

// ---------------- launch ----------------
extern "C" void kernel_launch(void* const* d_in, const int* in_sizes, int n_in,
                              void* d_out, int out_size) {
    const float* x    = (const float*)d_in[0];
    const float* w_ih = (const float*)d_in[1];
    const float* w_hh = (const float*)d_in[2];
    const float* b_ih = (const float*)d_in[3];
    const float* b_hh = (const float*)d_in[4];

    float *Xa, *Xb, *GXp, *Bp;
    cudaGetSymbolAddress((void**)&Xa, g_Xa);
    cudaGetSymbolAddress((void**)&Xb, g_Xb);
    cudaGetSymbolAddress((void**)&GXp, g_GX);
    cudaGetSymbolAddress((void**)&Bp, g_bias);
    float* Xbuf[2] = {Xa, Xb};

    bias_kernel<<<NLAYER * G4 / 256, 256>>>(b_ih, b_hh, Bp);

    dim3 tgrid(Tn / 32, Cn / 32, Bn), tblk(32, 8);
    tin_kernel<<<tgrid, tblk>>>(x, Xbuf[0]);

    int cur = 0;
    for (int l = 0; l < NLAYER; ++l) {
        gemm_gx<<<dim3(G4 / 128, Mn / 128), 256>>>(
            Xbuf[cur], w_ih + (size_t)l * G4 * Cn, Bp + (size_t)l * G4, GXp);
        scan_kernel<<<NCLUSTER * 8, 256>>>(
            Xbuf[cur], GXp, w_hh + (size_t)l * G4 * Cn,
            Xbuf[cur ^ 1], (l & 1) == 0 ? 1 : 0);
        cur ^= 1;
    }

    tout_kernel<<<tgrid, tblk>>>(Xbuf[cur], (float*)d_out);
}

// round 15
// speedup vs baseline: 1.8330x; 1.0007x over previous
#include <cuda_runtime.h>
#include <cstdint>

#define Tn 4000
#define Bn 16
#define Cn 256
#define G4 1024        // 4*C
#define Mn (Tn*Bn)     // 64000
#define NLAYER 12
#define NBPC 2         // batches per cluster
#define NCLUSTER (Bn / NBPC)   // 8 clusters of 8 CTAs = 64 CTAs (single wave)
#define HPAD 132       // padded half-stride (floats): 528B -> bank offset 4

// ---------------- scratch (device globals: allocation-free) ----------------
__device__ float g_Xa[(size_t)Mn * Cn];
__device__ float g_Xb[(size_t)Mn * Cn];
__device__ float g_GX[(size_t)Mn * G4];
__device__ float g_bias[NLAYER * G4];

// ---------------- packed f32x2 helpers ----------------
__device__ __forceinline__ void ffma2(unsigned long long& d, unsigned long long a, unsigned long long b) {
    asm("fma.rn.f32x2 %0, %1, %2, %0;" : "+l"(d) : "l"(a), "l"(b));
}
__device__ __forceinline__ unsigned long long pk(float a, float b) {
    unsigned long long r; asm("mov.b64 %0, {%1,%2};" : "=l"(r) : "f"(a), "f"(b)); return r;
}
__device__ __forceinline__ float2 unpk(unsigned long long v) {
    float2 r; asm("mov.b64 {%0,%1}, %2;" : "=f"(r.x), "=f"(r.y) : "l"(v)); return r;
}

// MUFU.TANH activations — single 16-cyc HW op; rel_err ~2.7e-6 end-to-end
__device__ __forceinline__ float tanh_mufu(float x) {
    float r; asm("tanh.approx.f32 %0, %1;" : "=f"(r) : "f"(x)); return r;
}
__device__ __forceinline__ float sig_mufu(float x) {
    return fmaf(0.5f, tanh_mufu(0.5f * x), 0.5f);
}

// ---------------- cluster primitives ----------------
__device__ __forceinline__ void st_peer(unsigned laddr, unsigned peer, float v) {
    asm volatile(
        "{\n\t.reg .u32 ra;\n\t"
        "mapa.shared::cluster.u32 ra, %0, %1;\n\t"
        "st.shared::cluster.f32 [ra], %2;\n\t}"
        :: "r"(laddr), "r"(peer), "f"(v) : "memory");
}
#define CLUSTER_SYNC() do { \
    asm volatile("barrier.cluster.arrive.aligned;" ::: "memory"); \
    asm volatile("barrier.cluster.wait.aligned;" ::: "memory"); } while (0)

// ---------------- tiny bias precompute ----------------
__global__ void bias_kernel(const float* __restrict__ bih, const float* __restrict__ bhh,
                            float* __restrict__ out) {
    int i = blockIdx.x * 256 + threadIdx.x;
    out[i] = bih[i] + bhh[i];
}

// ---------------- transpose in: x(B,C,L) -> X[t][b][c] ----------------
__global__ void tin_kernel(const float* __restrict__ x, float* __restrict__ X) {
    __shared__ float tile[32][33];
    int t0 = blockIdx.x * 32, c0 = blockIdx.y * 32, b = blockIdx.z;
    int tx = threadIdx.x, ty = threadIdx.y;
    #pragma unroll
    for (int i = 0; i < 32; i += 8)
        tile[ty + i][tx] = x[(size_t)b * Cn * Tn + (size_t)(c0 + ty + i) * Tn + t0 + tx];
    __syncthreads();
    #pragma unroll
    for (int i = 0; i < 32; i += 8)
        X[(size_t)(t0 + ty + i) * Bn * Cn + b * Cn + c0 + tx] = tile[tx][ty + i];
}

// ---------------- transpose out: X[t][b][c] -> out(B,C,L) ----------------
__global__ void tout_kernel(const float* __restrict__ X, float* __restrict__ out) {
    __shared__ float tile[32][33];
    int t0 = blockIdx.x * 32, c0 = blockIdx.y * 32, b = blockIdx.z;
    int tx = threadIdx.x, ty = threadIdx.y;
    #pragma unroll
    for (int i = 0; i < 32; i += 8)
        tile[ty + i][tx] = X[(size_t)(t0 + ty + i) * Bn * Cn + b * Cn + c0 + tx];
    __syncthreads();
    #pragma unroll
    for (int i = 0; i < 32; i += 8)
        out[(size_t)b * Cn * Tn + (size_t)(c0 + ty + i) * Tn + t0 + tx] = tile[tx][ty + i];
}

// ---------------- gx GEMM: GX[m][n] = X[m][k]*W[n][k] + bias[n] ----------------
__global__ __launch_bounds__(256, 2) void gemm_gx(
    const float* __restrict__ X, const float* __restrict__ W,
    const float* __restrict__ bsum, float* __restrict__ GXo)
{
    __shared__ __align__(16) float As[2][8][128];
    __shared__ __align__(16) float Bs[2][8][128];
    const int m0 = blockIdx.y * 128;
    const int n0 = blockIdx.x * 128;
    const int tid = threadIdx.x;
    const int tx = tid & 15, ty = tid >> 4;
    const int lr = tid >> 1;           // 0..127
    const int lk = (tid & 1) * 4;      // 0 or 4

    const float* Ag = X + (size_t)(m0 + lr) * 256 + lk;
    const float* Bg = W + (size_t)(n0 + lr) * 256 + lk;

    auto load_stage = [&](int s, int kc) {
        float4 av = *reinterpret_cast<const float4*>(Ag + kc * 8);
        float4 bv = *reinterpret_cast<const float4*>(Bg + kc * 8);
        As[s][lk + 0][lr] = av.x; As[s][lk + 1][lr] = av.y;
        As[s][lk + 2][lr] = av.z; As[s][lk + 3][lr] = av.w;
        Bs[s][lk + 0][lr] = bv.x; Bs[s][lk + 1][lr] = bv.y;
        Bs[s][lk + 2][lr] = bv.z; Bs[s][lk + 3][lr] = bv.w;
    };

    unsigned long long acc[8][4];
    #pragma unroll
    for (int i = 0; i < 8; i++)
        #pragma unroll
        for (int j = 0; j < 4; j++) acc[i][j] = 0ull;

    load_stage(0, 0);
    __syncthreads();

    for (int kc = 0; kc < 32; ++kc) {
        int s = kc & 1;
        if (kc < 31) load_stage(s ^ 1, kc + 1);
        #pragma unroll
        for (int k = 0; k < 8; k++) {
            float4 a0 = *reinterpret_cast<const float4*>(&As[s][k][ty * 8]);
            float4 a1 = *reinterpret_cast<const float4*>(&As[s][k][ty * 8 + 4]);
            float4 b0 = *reinterpret_cast<const float4*>(&Bs[s][k][tx * 8]);
            float4 b1 = *reinterpret_cast<const float4*>(&Bs[s][k][tx * 8 + 4]);
            unsigned long long bb0 = pk(b0.x, b0.y), bb1 = pk(b0.z, b0.w);
            unsigned long long bb2 = pk(b1.x, b1.y), bb3 = pk(b1.z, b1.w);
            float av[8] = {a0.x, a0.y, a0.z, a0.w, a1.x, a1.y, a1.z, a1.w};
            #pragma unroll
            for (int i = 0; i < 8; i++) {
                unsigned long long aa = pk(av[i], av[i]);
                ffma2(acc[i][0], aa, bb0);
                ffma2(acc[i][1], aa, bb1);
                ffma2(acc[i][2], aa, bb2);
                ffma2(acc[i][3], aa, bb3);
            }
        }
        __syncthreads();
    }

    float bias[8];
    #pragma unroll
    for (int j = 0; j < 8; j++) bias[j] = __ldg(&bsum[n0 + tx * 8 + j]);
    #pragma unroll
    for (int i = 0; i < 8; i++) {
        size_t m = (size_t)(m0 + ty * 8 + i);
        float o[8];
        #pragma unroll
        for (int jp = 0; jp < 4; jp++) {
            float2 v = unpk(acc[i][jp]);
            o[2 * jp] = v.x + bias[2 * jp];
            o[2 * jp + 1] = v.y + bias[2 * jp + 1];
        }
        float4* dst = reinterpret_cast<float4*>(&GXo[m * 1024 + n0 + tx * 8]);
        dst[0] = make_float4(o[0], o[1], o[2], o[3]);
        dst[1] = make_float4(o[4], o[5], o[6], o[7]);
    }
}

// ---------------- persistent LSTM scan (R14 + bank-conflict-free h buffer) --
// 8 clusters of 8 CTAs (64 CTAs, single wave); cluster cl advances batches
// {2cl, 2cl+1}. Lane layout: s = lane&3 (gate), kh = lane>>4 (K-half = batch),
// unit = warp*4 + ((lane>>2)&3), col = rank*32+unit.
// h buffer padded: h_s[par][batch][half][132] (half-stride 528B = bank +4,
// batch-stride 1056B = bank +8) -> every LDS.128 in the dot is single-phase
// (lanes 0-15 banks {b..b+3}, lanes 16-31 banks {b+4..b+7}).
__global__ void __cluster_dims__(8, 1, 1) __launch_bounds__(256, 1)
scan_kernel(const float* __restrict__ Xin, const float* __restrict__ GX,
            const float* __restrict__ Whh, float* __restrict__ Xout, int is_even)
{
    unsigned rank;
    asm("mov.u32 %0, %%cluster_ctarank;" : "=r"(rank));
    const int cl = blockIdx.x >> 3;
    const int b0 = cl * NBPC;
    const int tid = threadIdx.x;
    const int warp = tid >> 5, lane = tid & 31;
    const int s = lane & 3;                        // gate (i,f,g,o)
    const int kh = lane >> 4;                      // K-half = batch index
    const int unit = warp * 4 + ((lane >> 2) & 3); // 0..31
    const int col = (int)rank * 32 + unit;         // hidden index 0..255
    const int grow = s * 256 + col;                // W_hh row
    const int bsel = b0 + kh;
    const int half = (int)rank >> 2;               // which K-half col lives in
    const int hidx = col & 127;                    // index within the half

    __shared__ __align__(16) float h_s[2][NBPC][2][HPAD];

    // K-half weights for this lane's gate row: 128 fp32 register-resident
    ulonglong2 w[32];
    const ulonglong2* wp = reinterpret_cast<const ulonglong2*>(Whh + (size_t)grow * 256 + kh * 128);
    #pragma unroll
    for (int i = 0; i < 32; i++) w[i] = wp[i];

    for (int i = tid; i < 2 * NBPC * 2 * HPAD; i += 256)
        (&h_s[0][0][0][0])[i] = 0.f;
    float c_state = 0.f;
    __syncthreads();
    CLUSTER_SYNC();

    const float* gxp = GX + (size_t)bsel * G4 + grow;
    float gxv = __ldg(gxp);
    auto src_of = [&](int t) { return is_even ? (t % 400) * 10 + (t / 400) : t; };
    const bool writer = (s == 1);   // one lane per (unit,batch) writes Xout
    float xres = writer ? __ldg(Xin + ((size_t)src_of(0) * Bn + bsel) * Cn + col) : 0.f;

    for (int t = 0; t < Tn; ++t) {
        const int par = t & 1;

        // prefetch next step's gx/xres (LDG flight overlaps dot + barrier)
        float gxn = 0.f, xresn = 0.f;
        if (t + 1 < Tn) {
            gxn = __ldg(gxp + (size_t)(t + 1) * (Bn * G4));
            if (writer)
                xresn = __ldg(Xin + ((size_t)src_of(t + 1) * Bn + bsel) * Cn + col);
        }

        // both-batch dot over this lane's K-half (128 FFMA2, 64 LDS.128,
        // conflict-free: kh groups hit disjoint bank quads)
        const ulonglong2* hA = reinterpret_cast<const ulonglong2*>(&h_s[par][0][kh][0]);
        const ulonglong2* hB = reinterpret_cast<const ulonglong2*>(&h_s[par][1][kh][0]);
        unsigned long long a00 = 0, a01 = 0, a10 = 0, a11 = 0;
        #pragma unroll
        for (int i = 0; i < 32; i++) {
            ulonglong2 xA = hA[i], xB = hB[i];
            ffma2(a00, w[i].x, xA.x); ffma2(a01, w[i].y, xA.y);
            ffma2(a10, w[i].x, xB.x); ffma2(a11, w[i].y, xB.y);
        }
        float2 f0 = unpk(a00), f1 = unpk(a01);
        float p0 = (f0.x + f0.y) + (f1.x + f1.y);
        float2 f2 = unpk(a10), f3 = unpk(a11);
        float p1 = (f2.x + f2.y) + (f3.x + f3.y);
        p0 += __shfl_xor_sync(0xffffffffu, p0, 16);   // fold K-halves
        p1 += __shfl_xor_sync(0xffffffffu, p1, 16);

        // lane's batch = kh; one gate activation per lane (MUFU.TANH)
        float tot = (kh ? p1 : p0) + gxv;
        float act = (s == 2) ? tanh_mufu(tot) : sig_mufu(tot);
        gxv = gxn;

        // gather the 4 gates of this unit (within same kh group)
        const int base = lane & ~3;
        float iv = __shfl_sync(0xffffffffu, act, base);
        float fv = __shfl_sync(0xffffffffu, act, base | 1);
        float gv = __shfl_sync(0xffffffffu, act, base | 2);
        float ov = __shfl_sync(0xffffffffu, act, base | 3);

        c_state = fv * c_state + iv * gv;             // replicated across lanes
        float hv = ov * tanh_mufu(c_state);

        const int nb = par ^ 1;
        if (s == 0) h_s[nb][kh][half][hidx] = hv;     // local copy
        if (t + 1 < Tn) {
            // lane's gate slot covers peers {s+1, s+5}: all 7 peers covered
            unsigned laddr = (unsigned)__cvta_generic_to_shared(&h_s[nb][kh][half][hidx]);
            st_peer(laddr, (rank + (unsigned)s + 1u) & 7u, hv);
            if (s < 3)
                st_peer(laddr, (rank + (unsigned)s + 5u) & 7u, hv);
        }
        if (writer) {
            const int dst = is_even ? (t % 400) * 10 + (t / 400) : (Tn - 1 - t);
            Xout[((size_t)dst * Bn + bsel) * Cn + col] = xres + hv;
        }
        xres = xresn;

        CLUSTER_SYNC();   // publishes all DSMEM pushes for step t+1
    }
}

// ---------------- launch ----------------
extern "C" void kernel_launch(void* const* d_in, const int* in_sizes, int n_in,
                              void* d_out, int out_size) {
    const float* x    = (const float*)d_in[0];
    const float* w_ih = (const float*)d_in[1];
    const float* w_hh = (const float*)d_in[2];
    const float* b_ih = (const float*)d_in[3];
    const float* b_hh = (const float*)d_in[4];

    float *Xa, *Xb, *GXp, *Bp;
    cudaGetSymbolAddress((void**)&Xa, g_Xa);
    cudaGetSymbolAddress((void**)&Xb, g_Xb);
    cudaGetSymbolAddress((void**)&GXp, g_GX);
    cudaGetSymbolAddress((void**)&Bp, g_bias);
    float* Xbuf[2] = {Xa, Xb};

    bias_kernel<<<NLAYER * G4 / 256, 256>>>(b_ih, b_hh, Bp);

    dim3 tgrid(Tn / 32, Cn / 32, Bn), tblk(32, 8);
    tin_kernel<<<tgrid, tblk>>>(x, Xbuf[0]);

    int cur = 0;
    for (int l = 0; l < NLAYER; ++l) {
        gemm_gx<<<dim3(G4 / 128, Mn / 128), 256>>>(
            Xbuf[cur], w_ih + (size_t)l * G4 * Cn, Bp + (size_t)l * G4, GXp);
        scan_kernel<<<NCLUSTER * 8, 256>>>(
            Xbuf[cur], GXp, w_hh + (size_t)l * G4 * Cn,
            Xbuf[cur ^ 1], (l & 1) == 0 ? 1 : 0);
        cur ^= 1;
    }

    tout_kernel<<<tgrid, tblk>>>(Xbuf[cur], (float*)d_out);
}